// round 1
// baseline (speedup 1.0000x reference)
#include <cuda_runtime.h>
#include <cuda_fp16.h>
#include <math.h>
#include <stdint.h>

#define N_NODES 8192
#define IN_F    512
#define OUT_F   64

// Scratch (device globals; no allocation allowed)
__device__ float  d_h[N_NODES * OUT_F];        // h = X @ W
__device__ float  d_r[N_NODES];                // r_j = h[j] . a_right
__device__ float  d_pmax[32];                  // per-block maxima of r
__device__ __half d_HpT[72 * N_NODES];         // transposed [w*h | w | pad], n-major

// ---------------------------------------------------------------------------
// K1: h = X @ W   (8192x512 @ 512x64, fp32)
// Block: 256 threads, 64 rows x 64 cols tile; each thread 16 outputs.
// ---------------------------------------------------------------------------
__global__ void k1_hgemm(const float* __restrict__ X, const float* __restrict__ W) {
    __shared__ float Xs[64][65];
    __shared__ float Ws[64][64];
    const int tid  = threadIdx.x;
    const int r    = tid & 63;
    const int cg   = tid >> 6;          // 0..3, 16 cols each
    const int row0 = blockIdx.x * 64;

    float acc[16];
#pragma unroll
    for (int i = 0; i < 16; ++i) acc[i] = 0.f;

    for (int kc = 0; kc < IN_F; kc += 64) {
#pragma unroll
        for (int it = 0; it < 16; ++it) {
            int idx = it * 256 + tid;
            int rr = idx >> 6, cc = idx & 63;
            Xs[rr][cc] = X[(size_t)(row0 + rr) * IN_F + kc + cc];
            Ws[rr][cc] = W[(size_t)(kc + rr) * OUT_F + cc];
        }
        __syncthreads();
#pragma unroll 8
        for (int kk = 0; kk < 64; ++kk) {
            float a = Xs[r][kk];
            const float4* w4 = (const float4*)&Ws[kk][cg * 16];
            float4 w0 = w4[0], w1 = w4[1], w2 = w4[2], w3 = w4[3];
            acc[0]  += a * w0.x; acc[1]  += a * w0.y; acc[2]  += a * w0.z; acc[3]  += a * w0.w;
            acc[4]  += a * w1.x; acc[5]  += a * w1.y; acc[6]  += a * w1.z; acc[7]  += a * w1.w;
            acc[8]  += a * w2.x; acc[9]  += a * w2.y; acc[10] += a * w2.z; acc[11] += a * w2.w;
            acc[12] += a * w3.x; acc[13] += a * w3.y; acc[14] += a * w3.z; acc[15] += a * w3.w;
        }
        __syncthreads();
    }
    float* hp = &d_h[(size_t)(row0 + r) * OUT_F + cg * 16];
#pragma unroll
    for (int i = 0; i < 16; ++i) hp[i] = acc[i];
}

// ---------------------------------------------------------------------------
// K2: r_j = h[j] . a_right ; per-block max -> d_pmax
// ---------------------------------------------------------------------------
__global__ void k2_scores(const float* __restrict__ avec) {
    __shared__ float ar[64];
    __shared__ float red[256];
    const int tid = threadIdx.x;
    const int j   = blockIdx.x * 256 + tid;
    if (tid < 64) ar[tid] = avec[OUT_F + tid];   // a_right
    __syncthreads();

    const float4* h4 = (const float4*)&d_h[(size_t)j * OUT_F];
    float s = 0.f;
#pragma unroll
    for (int q = 0; q < 16; ++q) {
        float4 v = h4[q];
        s += v.x * ar[q * 4 + 0] + v.y * ar[q * 4 + 1]
           + v.z * ar[q * 4 + 2] + v.w * ar[q * 4 + 3];
    }
    d_r[j] = s;

    red[tid] = s;
    __syncthreads();
    for (int st = 128; st > 0; st >>= 1) {
        if (tid < st) red[tid] = fmaxf(red[tid], red[tid + st]);
        __syncthreads();
    }
    if (tid == 0) d_pmax[blockIdx.x] = red[0];
}

// ---------------------------------------------------------------------------
// K3: w_j = exp(r_j - m); build HpT[c][j] (fp16, n-major):
//     c<64: w*h[j][c];  c==64: w;  c in 65..71: 0 (padding)
// 64 blocks x 128 threads (128 j per block)
// ---------------------------------------------------------------------------
__global__ void k3_build() {
    __shared__ float hs[128][65];
    __shared__ float smax;
    const int tid = threadIdx.x;
    const int j0  = blockIdx.x * 128;
    if (tid == 0) {
        float m = d_pmax[0];
#pragma unroll
        for (int i = 1; i < 32; ++i) m = fmaxf(m, d_pmax[i]);
        smax = m;
    }
#pragma unroll
    for (int it = 0; it < 64; ++it) {
        int idx = it * 128 + tid;
        int rr = idx >> 6, cc = idx & 63;
        hs[rr][cc] = d_h[(size_t)(j0 + rr) * OUT_F + cc];
    }
    __syncthreads();
    float w = expf(d_r[j0 + tid] - smax);
#pragma unroll
    for (int c = 0; c < 72; ++c) {
        float v = (c < 64) ? w * hs[tid][c] : ((c == 64) ? w : 0.f);
        d_HpT[(size_t)c * N_NODES + j0 + tid] = __float2half(v);
    }
}

// ---------------------------------------------------------------------------
// K4: C[8192 x 72] = A(0/1) @ Hp, then out = elu(num/den)
// 128 CTAs x 128 threads (4 warps). CTA: 64 rows, all 72 cols. KC = 64.
// Double-buffered smem, int32->fp16 convert on the fly, m16n8k16 mma.
// ---------------------------------------------------------------------------
__device__ __forceinline__ void mma16816(float* c,
    uint32_t a0, uint32_t a1, uint32_t a2, uint32_t a3,
    uint32_t b0, uint32_t b1) {
    asm volatile(
        "mma.sync.aligned.m16n8k16.row.col.f32.f16.f16.f32 "
        "{%0,%1,%2,%3},{%4,%5,%6,%7},{%8,%9},{%0,%1,%2,%3};\n"
        : "+f"(c[0]), "+f"(c[1]), "+f"(c[2]), "+f"(c[3])
        : "r"(a0), "r"(a1), "r"(a2), "r"(a3), "r"(b0), "r"(b1));
}

__device__ __forceinline__ float elu1(float x) {
    return x > 0.f ? x : expm1f(x);
}

__global__ void __launch_bounds__(128)
k4_main(const int* __restrict__ adj, float* __restrict__ out) {
    __shared__ __half As[2][64][72];   // rows x k, fp16
    __shared__ __half Bs[2][72][72];   // n x k,  fp16  (Hp transposed chunk)

    const int tid  = threadIdx.x;
    const int warp = tid >> 5;
    const int lane = tid & 31;
    const int g    = lane >> 2;   // 0..7
    const int t    = lane & 3;    // 0..3
    const int row0 = blockIdx.x * 64;

    float acc[9][4];
#pragma unroll
    for (int n = 0; n < 9; ++n)
#pragma unroll
        for (int i = 0; i < 4; ++i) acc[n][i] = 0.f;

    const int4* adj4 = (const int4*)adj;
    const int4* hp4  = (const int4*)d_HpT;

    int4 aReg[8];
    int4 bReg[5];

    // --- prefetch helpers (inlined) ---
    auto loadA = [&](int kc) {
#pragma unroll
        for (int q = 0; q < 8; ++q) {
            int idx = q * 128 + tid;           // 0..1023 int4 (64 rows x 16 int4)
            int rr = idx >> 4, c4 = idx & 15;
            aReg[q] = adj4[(size_t)(row0 + rr) * 2048 + (kc >> 2) + c4];
        }
    };
    auto storeA = [&](int buf) {
#pragma unroll
        for (int q = 0; q < 8; ++q) {
            int idx = q * 128 + tid;
            int rr = idx >> 4, c4 = idx & 15;
            uint32_t h01 = (aReg[q].x != 0 ? 0x3C00u : 0u) | (aReg[q].y != 0 ? 0x3C000000u : 0u);
            uint32_t h23 = (aReg[q].z != 0 ? 0x3C00u : 0u) | (aReg[q].w != 0 ? 0x3C000000u : 0u);
            *(uint2*)&As[buf][rr][c4 * 4] = make_uint2(h01, h23);
        }
    };
    auto loadB = [&](int kc) {
#pragma unroll
        for (int q = 0; q < 5; ++q) {
            int idx = q * 128 + tid;           // 576 int4 (72 rows x 8 int4)
            if (idx < 576) {
                int rr = idx >> 3, s = idx & 7;
                bReg[q] = hp4[(size_t)rr * 1024 + (kc >> 3) + s];
            }
        }
    };
    auto storeB = [&](int buf) {
#pragma unroll
        for (int q = 0; q < 5; ++q) {
            int idx = q * 128 + tid;
            if (idx < 576) {
                int rr = idx >> 3, s = idx & 7;
                *(int4*)&Bs[buf][rr][s * 8] = bReg[q];
            }
        }
    };

    // --- pipeline ---
    loadA(0); loadB(0);
    storeA(0); storeB(0);
    __syncthreads();

    const int rb = warp * 16;
    for (int c = 0; c < 128; ++c) {
        int cb = c & 1;
        if (c < 127) { loadA((c + 1) * 64); loadB((c + 1) * 64); }

#pragma unroll
        for (int ks = 0; ks < 4; ++ks) {
            int kk = ks * 16 + 2 * t;
            uint32_t a0 = *(const uint32_t*)&As[cb][rb + g][kk];
            uint32_t a1 = *(const uint32_t*)&As[cb][rb + g + 8][kk];
            uint32_t a2 = *(const uint32_t*)&As[cb][rb + g][kk + 8];
            uint32_t a3 = *(const uint32_t*)&As[cb][rb + g + 8][kk + 8];
#pragma unroll
            for (int nt = 0; nt < 9; ++nt) {
                uint32_t b0 = *(const uint32_t*)&Bs[cb][nt * 8 + g][kk];
                uint32_t b1 = *(const uint32_t*)&Bs[cb][nt * 8 + g][kk + 8];
                mma16816(acc[nt], a0, a1, a2, a3, b0, b1);
            }
        }

        if (c < 127) { storeA(cb ^ 1); storeB(cb ^ 1); }
        __syncthreads();
    }

    // --- epilogue: den = col 64 (n-tile 8, local col 0 -> lanes with t==0) ---
    const unsigned full = 0xffffffffu;
    float den_lo = __shfl_sync(full, acc[8][0], (lane >> 2) << 2);
    float den_hi = __shfl_sync(full, acc[8][2], (lane >> 2) << 2);
    float inv_lo = 1.f / den_lo;
    float inv_hi = 1.f / den_hi;

    const int rlo = row0 + rb + g;
    const int rhi = rlo + 8;
#pragma unroll
    for (int nt = 0; nt < 8; ++nt) {
        int c0 = nt * 8 + 2 * t;
        float2 vlo = make_float2(elu1(acc[nt][0] * inv_lo), elu1(acc[nt][1] * inv_lo));
        float2 vhi = make_float2(elu1(acc[nt][2] * inv_hi), elu1(acc[nt][3] * inv_hi));
        *(float2*)&out[(size_t)rlo * OUT_F + c0] = vlo;
        *(float2*)&out[(size_t)rhi * OUT_F + c0] = vhi;
    }
}

// ---------------------------------------------------------------------------
extern "C" void kernel_launch(void* const* d_in, const int* in_sizes, int n_in,
                              void* d_out, int out_size) {
    const float* X    = (const float*)d_in[0];   // node_features 8192x512
    const int*   adj  = (const int*)  d_in[1];   // adjacency 8192x8192
    const float* W    = (const float*)d_in[2];   // weight 512x64
    const float* avec = (const float*)d_in[3];   // attention vector 128x1
    float* out = (float*)d_out;                  // 8192x64

    k1_hgemm<<<128, 256>>>(X, W);
    k2_scores<<<32, 256>>>(avec);
    k3_build<<<64, 128>>>();
    k4_main<<<128, 128>>>(adj, out);
}

// round 2
// speedup vs baseline: 1.5830x; 1.5830x over previous
#include <cuda_runtime.h>
#include <cuda_fp16.h>
#include <math.h>
#include <stdint.h>

#define N_NODES 8192
#define IN_F    512
#define OUT_F   64

// Scratch (device globals; no allocation allowed)
__device__ float  d_h[N_NODES * OUT_F];        // h = X @ W
__device__ float  d_r[N_NODES];                // r_j = h[j] . a_right
__device__ float  d_pmax[32];                  // per-block maxima of r
__device__ __half d_HpT[80 * N_NODES];         // transposed [w*h | w | pad], n-major

// ---------------------------------------------------------------------------
// common helpers
// ---------------------------------------------------------------------------
__device__ __forceinline__ void mma16816(float* c,
    uint32_t a0, uint32_t a1, uint32_t a2, uint32_t a3,
    uint32_t b0, uint32_t b1) {
    asm volatile(
        "mma.sync.aligned.m16n8k16.row.col.f32.f16.f16.f32 "
        "{%0,%1,%2,%3},{%4,%5,%6,%7},{%8,%9},{%0,%1,%2,%3};\n"
        : "+f"(c[0]), "+f"(c[1]), "+f"(c[2]), "+f"(c[3])
        : "r"(a0), "r"(a1), "r"(a2), "r"(a3), "r"(b0), "r"(b1));
}

__device__ __forceinline__ void cpa16(void* dst, const void* src) {
    uint32_t d = (uint32_t)__cvta_generic_to_shared(dst);
    asm volatile("cp.async.cg.shared.global [%0], [%1], 16;\n" :: "r"(d), "l"(src));
}
#define CP_COMMIT() asm volatile("cp.async.commit_group;\n" ::: "memory")
#define CP_WAIT(n)  asm volatile("cp.async.wait_group %0;\n" :: "n"(n) : "memory")

__device__ __forceinline__ float elu1(float x) {
    return x > 0.f ? x : expm1f(x);
}

// ---------------------------------------------------------------------------
// K1: h = X @ W  via fp16 mma (8192x512 @ 512x64), fp32 accumulate.
// 128 CTAs x 128 threads (4 warps). CTA = 64 rows. W fully resident in smem.
// X: 3-stage cp.async pipeline of raw fp32, converted at fragment build.
// ---------------------------------------------------------------------------
#define K1_XS   (3 * 64 * 68)                       // floats
#define K1_SMEM (K1_XS * 4 + 64 * 520 * 2)          // 118784 B

__global__ void __launch_bounds__(128)
k1_mma(const float* __restrict__ X, const float* __restrict__ W) {
    extern __shared__ char sm1[];
    float*  Xs = (float*)sm1;                        // [3][64][68]
    __half* Wt = (__half*)(sm1 + K1_XS * 4);         // [64 n][520 k]

    const int tid  = threadIdx.x;
    const int warp = tid >> 5;
    const int lane = tid & 31;
    const int g    = lane >> 2;
    const int t    = lane & 3;
    const int row0 = blockIdx.x * 64;

    // preload W transposed (fp16): element idx*4 = k*64 + n
    for (int i = 0; i < 64; ++i) {
        int idx = i * 128 + tid;
        int k = idx >> 4, n = (idx & 15) * 4;
        float4 f = ((const float4*)W)[idx];
        Wt[(n + 0) * 520 + k] = __float2half(f.x);
        Wt[(n + 1) * 520 + k] = __float2half(f.y);
        Wt[(n + 2) * 520 + k] = __float2half(f.z);
        Wt[(n + 3) * 520 + k] = __float2half(f.w);
    }

    auto issueX = [&](int c) {
        int kc = c * 64;
        float* Xd = Xs + (c % 3) * 64 * 68;
#pragma unroll
        for (int q = 0; q < 8; ++q) {
            int idx = q * 128 + tid;
            int rr = idx >> 4, c4 = idx & 15;
            cpa16(Xd + rr * 68 + c4 * 4,
                  X + (size_t)(row0 + rr) * IN_F + kc + c4 * 4);
        }
    };
    issueX(0); CP_COMMIT();
    issueX(1); CP_COMMIT();

    float acc[8][4];
#pragma unroll
    for (int n = 0; n < 8; ++n)
#pragma unroll
        for (int i = 0; i < 4; ++i) acc[n][i] = 0.f;

    const int rb = warp * 16;
    for (int c = 0; c < 8; ++c) {
        CP_WAIT(1);
        __syncthreads();
        if (c + 2 < 8) issueX(c + 2);
        CP_COMMIT();

        const float* Xst = Xs + (c % 3) * 64 * 68;
#pragma unroll
        for (int ks = 0; ks < 4; ++ks) {
            int kk = ks * 16 + 2 * t;
            float2 f;
            __half2 h2;
            f = *(const float2*)&Xst[(rb + g) * 68 + kk];
            h2 = __float22half2_rn(f); uint32_t a0 = *(uint32_t*)&h2;
            f = *(const float2*)&Xst[(rb + g + 8) * 68 + kk];
            h2 = __float22half2_rn(f); uint32_t a1 = *(uint32_t*)&h2;
            f = *(const float2*)&Xst[(rb + g) * 68 + kk + 8];
            h2 = __float22half2_rn(f); uint32_t a2 = *(uint32_t*)&h2;
            f = *(const float2*)&Xst[(rb + g + 8) * 68 + kk + 8];
            h2 = __float22half2_rn(f); uint32_t a3 = *(uint32_t*)&h2;

            int kg = c * 64 + kk;
#pragma unroll
            for (int nt = 0; nt < 8; ++nt) {
                int n = nt * 8 + g;
                uint32_t b0 = *(const uint32_t*)&Wt[n * 520 + kg];
                uint32_t b1 = *(const uint32_t*)&Wt[n * 520 + kg + 8];
                mma16816(acc[nt], a0, a1, a2, a3, b0, b1);
            }
        }
    }

    const int rlo = row0 + rb + g;
    const int rhi = rlo + 8;
#pragma unroll
    for (int nt = 0; nt < 8; ++nt) {
        int c0 = nt * 8 + 2 * t;
        *(float2*)&d_h[(size_t)rlo * OUT_F + c0] = make_float2(acc[nt][0], acc[nt][1]);
        *(float2*)&d_h[(size_t)rhi * OUT_F + c0] = make_float2(acc[nt][2], acc[nt][3]);
    }
}

// ---------------------------------------------------------------------------
// K2: r_j = h[j] . a_right ; per-block max -> d_pmax
// ---------------------------------------------------------------------------
__global__ void k2_scores(const float* __restrict__ avec) {
    __shared__ float ar[64];
    __shared__ float red[256];
    const int tid = threadIdx.x;
    const int j   = blockIdx.x * 256 + tid;
    if (tid < 64) ar[tid] = avec[OUT_F + tid];   // a_right
    __syncthreads();

    const float4* h4 = (const float4*)&d_h[(size_t)j * OUT_F];
    float s = 0.f;
#pragma unroll
    for (int q = 0; q < 16; ++q) {
        float4 v = h4[q];
        s += v.x * ar[q * 4 + 0] + v.y * ar[q * 4 + 1]
           + v.z * ar[q * 4 + 2] + v.w * ar[q * 4 + 3];
    }
    d_r[j] = s;

    red[tid] = s;
    __syncthreads();
    for (int st = 128; st > 0; st >>= 1) {
        if (tid < st) red[tid] = fmaxf(red[tid], red[tid + st]);
        __syncthreads();
    }
    if (tid == 0) d_pmax[blockIdx.x] = red[0];
}

// ---------------------------------------------------------------------------
// K3: w_j = exp(r_j - m); build HpT[c][j] (fp16, n-major, padded to 80):
//     c<64: w*h[j][c];  c==64: w;  c in 65..79: 0
// ---------------------------------------------------------------------------
__global__ void k3_build() {
    __shared__ float hs[128][65];
    __shared__ float smax;
    const int tid = threadIdx.x;
    const int j0  = blockIdx.x * 128;
    if (tid == 0) {
        float m = d_pmax[0];
#pragma unroll
        for (int i = 1; i < 32; ++i) m = fmaxf(m, d_pmax[i]);
        smax = m;
    }
#pragma unroll
    for (int it = 0; it < 64; ++it) {
        int idx = it * 128 + tid;
        int rr = idx >> 6, cc = idx & 63;
        hs[rr][cc] = d_h[(size_t)(j0 + rr) * OUT_F + cc];
    }
    __syncthreads();
    float w = expf(d_r[j0 + tid] - smax);
#pragma unroll
    for (int c = 0; c < 80; ++c) {
        float v = (c < 64) ? w * hs[tid][c] : ((c == 64) ? w : 0.f);
        d_HpT[(size_t)c * N_NODES + j0 + tid] = __float2half(v);
    }
}

// ---------------------------------------------------------------------------
// K4: C[8192 x 80] = A(0/1 int32) @ Hp(fp16), then out = elu(num/den)
// 128 CTAs x 256 threads (8 warps): warp = (rowgroup rg 0..3) x (ngroup ng 0..1)
// 4-stage cp.async pipeline; A staged as raw int32, converted at frag build.
// ---------------------------------------------------------------------------
#define K4_ASZ  (4 * 64 * 68)            // ints
#define K4_BSZ  (4 * 80 * 72)            // halves
#define K4_SMEM (K4_ASZ * 4 + K4_BSZ * 2 + 256)   // 115968 B

__global__ void __launch_bounds__(256)
k4_main(const int* __restrict__ adj, float* __restrict__ out) {
    extern __shared__ char sm4[];
    int*    Asm   = (int*)sm4;                          // [4][64][68]
    __half* Bsm   = (__half*)(sm4 + K4_ASZ * 4);        // [4][80][72]
    float*  den_s = (float*)(sm4 + K4_ASZ * 4 + K4_BSZ * 2);

    const int tid  = threadIdx.x;
    const int warp = tid >> 5;
    const int lane = tid & 31;
    const int g    = lane >> 2;
    const int t    = lane & 3;
    const int rg   = warp >> 1;
    const int ng   = warp & 1;
    const int row0 = blockIdx.x * 64;

    auto issue = [&](int c) {
        int kc = c * 64;
        int st = c & 3;
        int*    Ad = Asm + st * 64 * 68;
        __half* Bd = Bsm + st * 80 * 72;
#pragma unroll
        for (int q = 0; q < 4; ++q) {
            int idx = q * 256 + tid;
            int rr = idx >> 4, c4 = idx & 15;
            cpa16(Ad + rr * 68 + c4 * 4,
                  adj + (size_t)(row0 + rr) * N_NODES + kc + c4 * 4);
        }
#pragma unroll
        for (int q = 0; q < 3; ++q) {
            int idx = q * 256 + tid;
            if (idx < 640) {
                int rr = idx >> 3, s = idx & 7;
                cpa16(Bd + rr * 72 + s * 8,
                      d_HpT + (size_t)rr * N_NODES + kc + s * 8);
            }
        }
    };

    issue(0); CP_COMMIT();
    issue(1); CP_COMMIT();
    issue(2); CP_COMMIT();

    float acc[5][4];
#pragma unroll
    for (int n = 0; n < 5; ++n)
#pragma unroll
        for (int i = 0; i < 4; ++i) acc[n][i] = 0.f;

    const int r0l = rg * 16 + g;

    for (int c = 0; c < 128; ++c) {
        CP_WAIT(2);
        __syncthreads();
        if (c + 3 < 128) issue(c + 3);
        CP_COMMIT();

        const int st = c & 3;
        const int*    Ast = Asm + st * 64 * 68;
        const __half* Bst = Bsm + st * 80 * 72;

#pragma unroll
        for (int ks = 0; ks < 4; ++ks) {
            int kk = ks * 16 + 2 * t;
            int2 v;
            v = *(const int2*)&Ast[r0l * 68 + kk];
            uint32_t a0 = (v.x ? 0x3C00u : 0u) | (v.y ? 0x3C000000u : 0u);
            v = *(const int2*)&Ast[(r0l + 8) * 68 + kk];
            uint32_t a1 = (v.x ? 0x3C00u : 0u) | (v.y ? 0x3C000000u : 0u);
            v = *(const int2*)&Ast[r0l * 68 + kk + 8];
            uint32_t a2 = (v.x ? 0x3C00u : 0u) | (v.y ? 0x3C000000u : 0u);
            v = *(const int2*)&Ast[(r0l + 8) * 68 + kk + 8];
            uint32_t a3 = (v.x ? 0x3C00u : 0u) | (v.y ? 0x3C000000u : 0u);

#pragma unroll
            for (int nt = 0; nt < 5; ++nt) {
                int n = (ng * 5 + nt) * 8 + g;
                uint32_t b0 = *(const uint32_t*)&Bst[n * 72 + kk];
                uint32_t b1 = *(const uint32_t*)&Bst[n * 72 + kk + 8];
                mma16816(acc[nt], a0, a1, a2, a3, b0, b1);
            }
        }
    }

    // epilogue: den is column 64 = global n-tile 8 = (ng=1, nt=3, t=0)
    __syncthreads();
    if (ng == 1 && t == 0) {
        den_s[r0l]     = acc[3][0];
        den_s[r0l + 8] = acc[3][2];
    }
    __syncthreads();
    float inv_lo = 1.f / den_s[r0l];
    float inv_hi = 1.f / den_s[r0l + 8];

    const int rlo = row0 + r0l;
    const int rhi = rlo + 8;
#pragma unroll
    for (int nt = 0; nt < 5; ++nt) {
        int gt = ng * 5 + nt;
        if (gt >= 8) break;                 // tiles 8,9 are den/padding, not output
        int c0 = gt * 8 + 2 * t;
        float2 vlo = make_float2(elu1(acc[nt][0] * inv_lo), elu1(acc[nt][1] * inv_lo));
        float2 vhi = make_float2(elu1(acc[nt][2] * inv_hi), elu1(acc[nt][3] * inv_hi));
        *(float2*)&out[(size_t)rlo * OUT_F + c0] = vlo;
        *(float2*)&out[(size_t)rhi * OUT_F + c0] = vhi;
    }
}

// ---------------------------------------------------------------------------
extern "C" void kernel_launch(void* const* d_in, const int* in_sizes, int n_in,
                              void* d_out, int out_size) {
    const float* X    = (const float*)d_in[0];   // node_features 8192x512
    const int*   adj  = (const int*)  d_in[1];   // adjacency 8192x8192
    const float* W    = (const float*)d_in[2];   // weight 512x64
    const float* avec = (const float*)d_in[3];   // attention vector 128x1
    float* out = (float*)d_out;                  // 8192x64

    cudaFuncSetAttribute(k1_mma, cudaFuncAttributeMaxDynamicSharedMemorySize, K1_SMEM);
    cudaFuncSetAttribute(k4_main, cudaFuncAttributeMaxDynamicSharedMemorySize, K4_SMEM);

    k1_mma<<<128, 128, K1_SMEM>>>(X, W);
    k2_scores<<<32, 256>>>(avec);
    k3_build<<<64, 128>>>();
    k4_main<<<128, 256, K4_SMEM>>>(adj, out);
}